// round 6
// baseline (speedup 1.0000x reference)
#include <cuda_runtime.h>
#include <cuda_bf16.h>

#define BD 512
#define DD 512
#define NL 3
#define NK 100
#define NTHREADS 256
#define BETA 98.999992f

// One block per batch row; h lives in smem across all 3 layers.
// FAST PATH (linear phi, detected): sum_i lam*sat(h_i+eta*o) is computed in
// O(D) per layer via per-o histograms + one float4 block scan:
//   element i is zero-clamped for o <= floor(-h_i/eta)  (suffix sums Z)
//   element i is one-clamped  for o >= ceil((1-h_i)/eta) (prefix sums U)
//   interior contributes lam*h_i + co*lam.
// FALLBACK: lane-replicated table gather (exact piecewise-linear phi).
__global__ __launch_bounds__(NTHREADS) void sprecher_kernel(
    const float* __restrict__ x,
    const float* __restrict__ lambdas,
    const float* __restrict__ eta,
    const float* __restrict__ phi_log_inc,
    const float* __restrict__ Phi_coeffs,
    const float* __restrict__ dc_p, const float* __restrict__ dr_p,
    const float* __restrict__ cc_p, const float* __restrict__ cr_p,
    const float* __restrict__ res_w,
    const float* __restrict__ output_scale,
    float* __restrict__ out)
{
    __shared__ float  h[DD];
    __shared__ __align__(16) float2 phi_tab[99 * 32]; // fallback table; fast path overlays float4 hist4[512]
    __shared__ float4 hl4[DD / 2];                    // fallback broadcast quads
    __shared__ float  Phic[NK];
    __shared__ float  coef[NK];
    __shared__ float  s_cmin, s_cmax, s_inv, s_gamma, s_Tl, s_Tlh;
    __shared__ float  rA[8], rB[8], rC[8], rD[8], rE[8];
    __shared__ float4 wsum4[8];

    float4* hist4 = reinterpret_cast<float4*>(phi_tab);

    const int b    = blockIdx.x;
    const int tid  = threadIdx.x;
    const int lane = tid & 31;
    const int wid  = tid >> 5;

    for (int i = tid; i < DD; i += NTHREADS) h[i] = x[b * DD + i];

    const float dcv = dc_p[0], drv = dr_p[0], ccv = cc_p[0], crv = cr_p[0];
    const float in_min = dcv - drv, in_max = dcv + drv;
    const float o_min  = ccv - crv, o_max  = ccv + crv;
    const float cap_scale = 99.0f / (in_max - in_min);
    const float2* __restrict__ tabL = (const float2*)phi_tab + lane;

    for (int l = 0; l < NL; ++l) {
        const float etal = eta[l];
        const float rw   = res_w[l];

        __syncthreads();                                   // B0: h ready, prev smem reads done

        float sp = 0.f, pc = 0.f;
        if (tid < NK) {
            float v = phi_log_inc[l * NK + tid];
            sp = (v > 20.f) ? v : log1pf(expf(v));         // softplus
            coef[tid] = sp;
            pc = Phi_coeffs[l * NK + tid];
            Phic[tid] = pc;
        }

        // this thread's two elements (2*tid, 2*tid+1)
        const float2 lm = ((const float2*)(lambdas + l * DD))[tid];
        const float hx = h[2 * tid], hz = h[2 * tid + 1];

        // block reductions: T_l, T_lh; min/max Phic; sum softplus
        float tl  = lm.x + lm.y;
        float tlh = lm.x * hx + lm.y * hz;
        float mn  = (tid < NK) ? pc : 3.0e38f;
        float mx  = (tid < NK) ? pc : -3.0e38f;
        float ss  = sp;
        #pragma unroll
        for (int off = 16; off > 0; off >>= 1) {
            tl  += __shfl_xor_sync(~0u, tl,  off);
            tlh += __shfl_xor_sync(~0u, tlh, off);
            mn   = fminf(mn, __shfl_xor_sync(~0u, mn, off));
            mx   = fmaxf(mx, __shfl_xor_sync(~0u, mx, off));
            ss  += __shfl_xor_sync(~0u, ss, off);
        }
        if (lane == 0) { rA[wid]=tl; rB[wid]=tlh; rC[wid]=mn; rD[wid]=mx; rE[wid]=ss; }
        __syncthreads();                                   // B1
        if (tid == 0) {
            float Tl=0.f, Tlh=0.f, Mn=3.0e38f, Mx=-3.0e38f, Ss=0.f;
            #pragma unroll
            for (int w = 0; w < 8; ++w) {
                Tl += rA[w]; Tlh += rB[w];
                Mn = fminf(Mn, rC[w]); Mx = fmaxf(Mx, rD[w]); Ss += rE[w];
            }
            s_Tl = Tl; s_Tlh = Tlh; s_cmin = Mn; s_cmax = Mx;
            s_gamma = coef[0] / (Ss + 1e-8f);
        }
        const float coef0 = coef[0];                       // visible after B1
        const int lin = __syncthreads_and(tid >= NK ||
                           fabsf(sp - coef0) <= 1e-6f * fabsf(coef0));  // B2

        const float co0 = etal * (float)tid;
        const float co1 = etal * (float)(tid + NTHREADS);
        float acc0, acc1;

        if (lin) {
            const float inv_eta = 1.0f / etal;
            const float4 z4 = make_float4(0.f, 0.f, 0.f, 0.f);
            hist4[tid] = z4; hist4[tid + NTHREADS] = z4;
            __syncthreads();                               // B3
            #pragma unroll
            for (int e = 0; e < 2; ++e) {
                const float hv = e ? hz : hx;
                const float lv = e ? lm.y : lm.x;
                if (hv <= 0.f) {                           // zero-clamped for o <= bz
                    int bz = __float2int_rd(-hv * inv_eta);
                    bz = min(bz, 511);
                    atomicAdd(&hist4[511 - bz].x, lv);
                    atomicAdd(&hist4[511 - bz].y, lv * hv);
                }
                int ou = __float2int_ru((1.0f - hv) * inv_eta);  // one-clamped for o >= ou
                ou = max(ou, 0);
                if (ou <= 511) {
                    atomicAdd(&hist4[ou].z, lv);
                    atomicAdd(&hist4[ou].w, lv * hv);
                }
            }
            __syncthreads();                               // B4
            // inclusive float4 scan over 512 bins (2 per thread)
            float4 a = hist4[2 * tid], c = hist4[2 * tid + 1];
            float4 s1 = make_float4(a.x + c.x, a.y + c.y, a.z + c.z, a.w + c.w);
            #pragma unroll
            for (int d = 1; d < 32; d <<= 1) {
                float nx = __shfl_up_sync(~0u, s1.x, d);
                float ny = __shfl_up_sync(~0u, s1.y, d);
                float nz = __shfl_up_sync(~0u, s1.z, d);
                float nw = __shfl_up_sync(~0u, s1.w, d);
                if (lane >= d) { s1.x += nx; s1.y += ny; s1.z += nz; s1.w += nw; }
            }
            if (lane == 31) wsum4[wid] = s1;
            __syncthreads();                               // B5
            float4 off4 = make_float4(0.f, 0.f, 0.f, 0.f);
            #pragma unroll
            for (int w = 0; w < 8; ++w)
                if (w < wid) {
                    float4 t = wsum4[w];
                    off4.x += t.x; off4.y += t.y; off4.z += t.z; off4.w += t.w;
                }
            float4 p1 = make_float4(off4.x + s1.x, off4.y + s1.y,
                                    off4.z + s1.z, off4.w + s1.w);
            float4 p0 = make_float4(p1.x - c.x, p1.y - c.y, p1.z - c.z, p1.w - c.w);
            hist4[2 * tid]     = p0;
            hist4[2 * tid + 1] = p1;
            __syncthreads();                               // B6
            const float Tl = s_Tl, Tlh = s_Tlh;
            const float g99 = 99.0f * s_gamma;
            const float base = s_gamma * Tl;
            {
                float4 Z = hist4[511 - tid];
                float4 U = hist4[tid];
                float Sl  = Tl  - Z.x - U.z;
                float Slh = Tlh - Z.y - U.w;
                float satsum = fmaf(co0, Sl, Slh) + U.z;
                acc0 = fmaf(g99, satsum, base);
            }
            {
                int o = tid + NTHREADS;
                float4 Z = hist4[511 - o];
                float4 U = hist4[o];
                float Sl  = Tl  - Z.x - U.z;
                float Slh = Tlh - Z.y - U.w;
                float satsum = fmaf(co1, Sl, Slh) + U.z;
                acc1 = fmaf(g99, satsum, base);
            }
        } else {
            // fallback: exact table-gather path
            if (tid == 0) {
                float cum = 0.f;
                for (int k = 0; k < NK; ++k) { cum += coef[k]; coef[k] = cum; }
                s_inv = 1.0f / (cum + 1e-8f);
            }
            hl4[tid] = make_float4(hx, lm.x, hz, lm.y);
            __syncthreads();
            {
                const float inv = s_inv;
                const float fix = 99.0f / BETA;
                for (int idx = tid; idx < 99 * 32; idx += NTHREADS) {
                    int k = idx >> 5;
                    float c0 = coef[k] * inv;
                    float dk = coef[k + 1] * inv - c0;
                    phi_tab[idx] = make_float2(dk * fix, fmaf(-(float)k, dk, c0));
                }
            }
            __syncthreads();
            acc0 = 0.f; acc1 = 0.f;
            #pragma unroll 4
            for (int i2 = 0; i2 < DD / 2; ++i2) {
                const float4 hv = hl4[i2];
                { float u = __saturatef(hv.x + co0) * BETA; float2 t = tabL[((int)u) * 32];
                  acc0 = fmaf(hv.y, fmaf(u, t.x, t.y), acc0); }
                { float u = __saturatef(hv.x + co1) * BETA; float2 t = tabL[((int)u) * 32];
                  acc1 = fmaf(hv.y, fmaf(u, t.x, t.y), acc1); }
                { float u = __saturatef(hv.z + co0) * BETA; float2 t = tabL[((int)u) * 32];
                  acc0 = fmaf(hv.w, fmaf(u, t.x, t.y), acc0); }
                { float u = __saturatef(hv.z + co1) * BETA; float2 t = tabL[((int)u) * 32];
                  acc1 = fmaf(hv.w, fmaf(u, t.x, t.y), acc1); }
            }
        }

        // Epilogue: Phi spline + renorm + residual
        const float cmin = s_cmin, cmax = s_cmax;
        const float inv_norm = 1.0f / (cmax - cmin + 1e-8f);
        float act0, act1;
        {
            float s   = acc0 + (float)tid;
            float scv = fminf(fmaxf(s, in_min), in_max);
            float u   = (scv - in_min) * cap_scale;
            int   k   = (int)u; k = min(k, 98);
            float f   = u - (float)k;
            float c0  = Phic[k], c1 = Phic[k + 1];
            float raw = fmaf(f, c1 - c0, c0);
            float rn  = fminf(fmaxf((raw - cmin) * inv_norm, 0.f), 1.f);
            act0 = fmaf(o_max - o_min, rn, o_min) + rw * h[tid];
        }
        {
            float s   = acc1 + (float)(tid + NTHREADS);
            float scv = fminf(fmaxf(s, in_min), in_max);
            float u   = (scv - in_min) * cap_scale;
            int   k   = (int)u; k = min(k, 98);
            float f   = u - (float)k;
            float c0  = Phic[k], c1 = Phic[k + 1];
            float raw = fmaf(f, c1 - c0, c0);
            float rn  = fminf(fmaxf((raw - cmin) * inv_norm, 0.f), 1.f);
            act1 = fmaf(o_max - o_min, rn, o_min) + rw * h[tid + NTHREADS];
        }

        if (l < NL - 1) {
            __syncthreads();
            h[tid]            = act0;
            h[tid + NTHREADS] = act1;
        } else {
            float v = act0 + act1;
            #pragma unroll
            for (int off = 16; off > 0; off >>= 1)
                v += __shfl_xor_sync(0xffffffffu, v, off);
            if (lane == 0) rA[wid] = v;
            __syncthreads();
            if (tid == 0) {
                float r = 0.f;
                #pragma unroll
                for (int w = 0; w < NTHREADS / 32; ++w) r += rA[w];
                out[b] = r * output_scale[0];
            }
        }
    }
}

extern "C" void kernel_launch(void* const* d_in, const int* in_sizes, int n_in,
                              void* d_out, int out_size)
{
    const float* x            = (const float*)d_in[0];
    const float* lambdas      = (const float*)d_in[1];
    const float* eta          = (const float*)d_in[2];
    const float* phi_log_inc  = (const float*)d_in[3];
    const float* Phi_coeffs   = (const float*)d_in[4];
    const float* dc           = (const float*)d_in[5];
    const float* dr           = (const float*)d_in[6];
    const float* cc           = (const float*)d_in[7];
    const float* cr           = (const float*)d_in[8];
    const float* res_w        = (const float*)d_in[9];
    const float* output_scale = (const float*)d_in[10];
    float* out = (float*)d_out;

    sprecher_kernel<<<BD, NTHREADS>>>(x, lambdas, eta, phi_log_inc, Phi_coeffs,
                                      dc, dr, cc, cr, res_w, output_scale, out);
}

// round 9
// speedup vs baseline: 2.9341x; 2.9341x over previous
#include <cuda_runtime.h>
#include <cuda_bf16.h>

#define BD 512
#define DD 512
#define NL 3
#define NK 100
#define NTHREADS 256
#define BETA 98.999992f

// One block per batch row; h lives in smem across all 3 layers.
// FAST PATH (linear phi): sat(h_i + eta*o) clamp state is o-independent when
// h_i >= 1 (always 1) or h_i <= -eta*511 (always 0). Compact the remaining
// "active" elements into a dense (h,lam) list and run the 2-inst/eval loop
// only over those. After layer 0 nearly everything saturates -> ~O(D) layers.
// FALLBACK: lane-replicated table gather (exact piecewise-linear phi).
__global__ __launch_bounds__(NTHREADS) void sprecher_kernel(
    const float* __restrict__ x,
    const float* __restrict__ lambdas,
    const float* __restrict__ eta,
    const float* __restrict__ phi_log_inc,
    const float* __restrict__ Phi_coeffs,
    const float* __restrict__ dc_p, const float* __restrict__ dr_p,
    const float* __restrict__ cc_p, const float* __restrict__ cr_p,
    const float* __restrict__ res_w,
    const float* __restrict__ output_scale,
    float* __restrict__ out)
{
    __shared__ float  h[DD];
    __shared__ __align__(16) float2 phi_tab[99 * 32]; // fallback table / fast-path compact list
    __shared__ float4 hl4[DD / 2];                    // fallback broadcast quads
    __shared__ float  Phic[NK];
    __shared__ float  coef[NK];
    __shared__ float  s_cmin, s_cmax, s_inv, s_gamma, s_Tl, s_S1;
    __shared__ int    s_nact;
    __shared__ float  rA[8], rB[8], rC[8], rD[8], rE[8];
    __shared__ int    wcnt[8];

    const int b    = blockIdx.x;
    const int tid  = threadIdx.x;
    const int lane = tid & 31;
    const int wid  = tid >> 5;

    for (int i = tid; i < DD; i += NTHREADS) h[i] = x[b * DD + i];

    const float dcv = dc_p[0], drv = dr_p[0], ccv = cc_p[0], crv = cr_p[0];
    const float in_min = dcv - drv, in_max = dcv + drv;
    const float o_min  = ccv - crv, o_max  = ccv + crv;
    const float cap_scale = 99.0f / (in_max - in_min);
    const float2* __restrict__ tabL = (const float2*)phi_tab + lane;

    for (int l = 0; l < NL; ++l) {
        const float etal = eta[l];
        const float rw   = res_w[l];

        __syncthreads();                                   // B0: h ready, prev smem reads done

        float sp = 0.f, pc = 0.f;
        if (tid < NK) {
            float v = phi_log_inc[l * NK + tid];
            sp = (v > 20.f) ? v : log1pf(expf(v));         // softplus
            coef[tid] = sp;
            pc = Phi_coeffs[l * NK + tid];
            Phic[tid] = pc;
        }

        // this thread's two elements (2*tid, 2*tid+1)
        const float2 lm = ((const float2*)(lambdas + l * DD))[tid];
        const float hx = h[2 * tid], hz = h[2 * tid + 1];

        // block reductions: T_lambda, S1 (lam where h>=1), Phic min/max, sum softplus
        const float one0 = (hx >= 1.0f) ? lm.x : 0.f;
        const float one1 = (hz >= 1.0f) ? lm.y : 0.f;
        float tl  = lm.x + lm.y;
        float s1  = one0 + one1;
        float mn  = (tid < NK) ? pc : 3.0e38f;
        float mx  = (tid < NK) ? pc : -3.0e38f;
        float ss  = sp;
        #pragma unroll
        for (int off = 16; off > 0; off >>= 1) {
            tl += __shfl_xor_sync(~0u, tl, off);
            s1 += __shfl_xor_sync(~0u, s1, off);
            mn  = fminf(mn, __shfl_xor_sync(~0u, mn, off));
            mx  = fmaxf(mx, __shfl_xor_sync(~0u, mx, off));
            ss += __shfl_xor_sync(~0u, ss, off);
        }
        if (lane == 0) { rA[wid]=tl; rB[wid]=s1; rC[wid]=mn; rD[wid]=mx; rE[wid]=ss; }
        __syncthreads();                                   // B1
        if (tid == 0) {
            float Tl=0.f, S1=0.f, Mn=3.0e38f, Mx=-3.0e38f, Ss=0.f;
            #pragma unroll
            for (int w = 0; w < 8; ++w) {
                Tl += rA[w]; S1 += rB[w];
                Mn = fminf(Mn, rC[w]); Mx = fmaxf(Mx, rD[w]); Ss += rE[w];
            }
            s_Tl = Tl; s_S1 = S1; s_cmin = Mn; s_cmax = Mx;
            s_gamma = coef[0] / (Ss + 1e-8f);
        }
        const float coef0 = coef[0];                       // visible after B1
        const int lin = __syncthreads_and(tid >= NK ||
                           fabsf(sp - coef0) <= 1e-6f * fabsf(coef0));  // B2

        const float co0 = etal * (float)tid;
        const float co1 = etal * (float)(tid + NTHREADS);
        float acc0 = 0.f, acc1 = 0.f;

        if (lin) {
            // ---- compact active elements: -eta*511 < h < 1 ----
            const float comax = etal * 511.0f;
            const bool a0 = (hx > -comax) && (hx < 1.0f);
            const bool a1 = (hz > -comax) && (hz < 1.0f);
            int c = (int)a0 + (int)a1;
            int incl = c;
            #pragma unroll
            for (int d = 1; d < 32; d <<= 1) {
                int n = __shfl_up_sync(~0u, incl, d);
                if (lane >= d) incl += n;
            }
            if (lane == 31) wcnt[wid] = incl;
            __syncthreads();                               // B3
            int wbase = 0;
            #pragma unroll
            for (int w = 0; w < 8; ++w) if (w < wid) wbase += wcnt[w];
            int pos = wbase + incl - c;
            if (a0) phi_tab[pos++] = make_float2(hx, lm.x);
            if (a1) phi_tab[pos]   = make_float2(hz, lm.y);
            if (tid == 0) {
                int tot = 0;
                #pragma unroll
                for (int w = 0; w < 8; ++w) tot += wcnt[w];
                if (tot & 1) { phi_tab[tot] = make_float2(0.f, 0.f); tot++; }
                s_nact = tot;
            }
            __syncthreads();                               // B4
            const int n2 = s_nact >> 1;
            const float4* __restrict__ lst = (const float4*)phi_tab;
            #pragma unroll 4
            for (int j = 0; j < n2; ++j) {
                const float4 hv = lst[j];    // (h_a, lam_a, h_b, lam_b)
                acc0 = fmaf(hv.y, __saturatef(hv.x + co0), acc0);
                acc1 = fmaf(hv.y, __saturatef(hv.x + co1), acc1);
                acc0 = fmaf(hv.w, __saturatef(hv.z + co0), acc0);
                acc1 = fmaf(hv.w, __saturatef(hv.z + co1), acc1);
            }
            const float g99  = 99.0f * s_gamma;
            const float base = s_gamma * s_Tl;
            const float S1v  = s_S1;
            acc0 = fmaf(g99, acc0 + S1v, base);
            acc1 = fmaf(g99, acc1 + S1v, base);
        } else {
            // ---- fallback: exact table-gather path ----
            if (tid == 0) {
                float cum = 0.f;
                for (int k = 0; k < NK; ++k) { cum += coef[k]; coef[k] = cum; }
                s_inv = 1.0f / (cum + 1e-8f);
            }
            hl4[tid] = make_float4(hx, lm.x, hz, lm.y);
            __syncthreads();
            {
                const float inv = s_inv;
                const float fix = 99.0f / BETA;
                for (int idx = tid; idx < 99 * 32; idx += NTHREADS) {
                    int k = idx >> 5;
                    float c0 = coef[k] * inv;
                    float dk = coef[k + 1] * inv - c0;
                    phi_tab[idx] = make_float2(dk * fix, fmaf(-(float)k, dk, c0));
                }
            }
            __syncthreads();
            #pragma unroll 4
            for (int i2 = 0; i2 < DD / 2; ++i2) {
                const float4 hv = hl4[i2];
                { float u = __saturatef(hv.x + co0) * BETA; float2 t = tabL[((int)u) * 32];
                  acc0 = fmaf(hv.y, fmaf(u, t.x, t.y), acc0); }
                { float u = __saturatef(hv.x + co1) * BETA; float2 t = tabL[((int)u) * 32];
                  acc1 = fmaf(hv.y, fmaf(u, t.x, t.y), acc1); }
                { float u = __saturatef(hv.z + co0) * BETA; float2 t = tabL[((int)u) * 32];
                  acc0 = fmaf(hv.w, fmaf(u, t.x, t.y), acc0); }
                { float u = __saturatef(hv.z + co1) * BETA; float2 t = tabL[((int)u) * 32];
                  acc1 = fmaf(hv.w, fmaf(u, t.x, t.y), acc1); }
            }
        }

        // Epilogue: Phi spline + renorm + residual
        const float cmin = s_cmin, cmax = s_cmax;
        const float inv_norm = 1.0f / (cmax - cmin + 1e-8f);
        float act0, act1;
        {
            float s   = acc0 + (float)tid;
            float scv = fminf(fmaxf(s, in_min), in_max);
            float u   = (scv - in_min) * cap_scale;
            int   k   = (int)u; k = min(k, 98);
            float f   = u - (float)k;
            float c0  = Phic[k], c1 = Phic[k + 1];
            float raw = fmaf(f, c1 - c0, c0);
            float rn  = fminf(fmaxf((raw - cmin) * inv_norm, 0.f), 1.f);
            act0 = fmaf(o_max - o_min, rn, o_min) + rw * h[tid];
        }
        {
            float s   = acc1 + (float)(tid + NTHREADS);
            float scv = fminf(fmaxf(s, in_min), in_max);
            float u   = (scv - in_min) * cap_scale;
            int   k   = (int)u; k = min(k, 98);
            float f   = u - (float)k;
            float c0  = Phic[k], c1 = Phic[k + 1];
            float raw = fmaf(f, c1 - c0, c0);
            float rn  = fminf(fmaxf((raw - cmin) * inv_norm, 0.f), 1.f);
            act1 = fmaf(o_max - o_min, rn, o_min) + rw * h[tid + NTHREADS];
        }

        if (l < NL - 1) {
            __syncthreads();
            h[tid]            = act0;
            h[tid + NTHREADS] = act1;
        } else {
            float v = act0 + act1;
            #pragma unroll
            for (int off = 16; off > 0; off >>= 1)
                v += __shfl_xor_sync(0xffffffffu, v, off);
            if (lane == 0) rA[wid] = v;
            __syncthreads();
            if (tid == 0) {
                float r = 0.f;
                #pragma unroll
                for (int w = 0; w < NTHREADS / 32; ++w) r += rA[w];
                out[b] = r * output_scale[0];
            }
        }
    }
}

extern "C" void kernel_launch(void* const* d_in, const int* in_sizes, int n_in,
                              void* d_out, int out_size)
{
    const float* x            = (const float*)d_in[0];
    const float* lambdas      = (const float*)d_in[1];
    const float* eta          = (const float*)d_in[2];
    const float* phi_log_inc  = (const float*)d_in[3];
    const float* Phi_coeffs   = (const float*)d_in[4];
    const float* dc           = (const float*)d_in[5];
    const float* dr           = (const float*)d_in[6];
    const float* cc           = (const float*)d_in[7];
    const float* cr           = (const float*)d_in[8];
    const float* res_w        = (const float*)d_in[9];
    const float* output_scale = (const float*)d_in[10];
    float* out = (float*)d_out;

    sprecher_kernel<<<BD, NTHREADS>>>(x, lambdas, eta, phi_log_inc, Phi_coeffs,
                                      dc, dr, cc, cr, res_w, output_scale, out);
}